// round 6
// baseline (speedup 1.0000x reference)
#include <cuda_runtime.h>
#include <cuda_bf16.h>
#include <cstdint>
#include <math.h>

#define N_    8
#define C_    256
#define H_    64
#define W_    64
#define K_    9
#define P_    4096          // 64*64
#define CK_   2304          // C_*K_
#define COUT_ 256
#define NCHUNK 72           // CK_/32
#define KC    32

// quantization scales (global, shared so both corrections have one dequant)
#define S_A   0.4f
#define S_B   8.0f
#define QA_H  (127.0f / S_A)
#define QA_E  (127.0f * 512.0f / S_A)
#define QB_H  (127.0f / S_B)
#define QB_E  (127.0f * 512.0f / S_B)
#define INV_Q ((S_A * S_B) / (127.0f * 127.0f * 512.0f))

// ------------------------------- scratch ------------------------------------
// cols hi (bf16, K-major [n][p][k*256+c]) and int8 pairs [n][p][chunk][qBh32|qeB32]
__device__ __nv_bfloat16 g_chi[(size_t)N_ * P_ * CK_];
__device__ int8_t        g_ci8[(size_t)N_ * P_ * CK_ * 2];
// weights: hi bf16 [cout][k*256+c]; int8 pairs [cout][chunk][qeA32|qAh32]
__device__ __nv_bfloat16 g_whi[COUT_ * CK_];
__device__ int8_t        g_wi8[COUT_ * CK_ * 2];

// ---------------- small PTX helpers (family-agnostic only) ------------------
__device__ __forceinline__ uint32_t smem_to_u32(const void* p) {
    uint32_t a;
    asm("{ .reg .u64 t; cvta.to.shared.u64 t, %1; cvt.u32.u64 %0, t; }"
        : "=r"(a) : "l"(p));
    return a;
}
__device__ __forceinline__ void cp16(uint32_t dst, const void* src) {
    asm volatile("cp.async.cg.shared.global [%0], [%1], 16;"
                 :: "r"(dst), "l"(src));
}
__device__ __forceinline__ void cp_commit() {
    asm volatile("cp.async.commit_group;" ::: "memory");
}
template <int NN>
__device__ __forceinline__ void cp_wait() {
    asm volatile("cp.async.wait_group %0;" :: "n"(NN) : "memory");
}
__device__ __forceinline__ void ldsm4(uint32_t* r, uint32_t addr) {
    asm volatile("ldmatrix.sync.aligned.m8n8.x4.shared.b16 {%0,%1,%2,%3}, [%4];"
        : "=r"(r[0]), "=r"(r[1]), "=r"(r[2]), "=r"(r[3]) : "r"(addr));
}
__device__ __forceinline__ void mma16816(float* d, const uint32_t* a,
                                         uint32_t b0, uint32_t b1) {
    asm volatile("mma.sync.aligned.m16n8k16.row.col.f32.bf16.bf16.f32 "
        "{%0,%1,%2,%3}, {%4,%5,%6,%7}, {%8,%9}, {%0,%1,%2,%3};"
        : "+f"(d[0]), "+f"(d[1]), "+f"(d[2]), "+f"(d[3])
        : "r"(a[0]), "r"(a[1]), "r"(a[2]), "r"(a[3]), "r"(b0), "r"(b1));
}
__device__ __forceinline__ void mma16832i(int32_t* d, const uint32_t* a,
                                          uint32_t b0, uint32_t b1) {
    asm volatile("mma.sync.aligned.m16n8k32.row.col.s32.s8.s8.s32 "
        "{%0,%1,%2,%3}, {%4,%5,%6,%7}, {%8,%9}, {%0,%1,%2,%3};"
        : "+r"(d[0]), "+r"(d[1]), "+r"(d[2]), "+r"(d[3])
        : "r"(a[0]), "r"(a[1]), "r"(a[2]), "r"(a[3]), "r"(b0), "r"(b1));
}
__device__ __forceinline__ int8_t q8(float v) {
    int t = __float2int_rn(v);
    t = max(-127, min(127, t));
    return (int8_t)t;
}

// ---------------------------------------------------------------------------
// Kernel 0: weight split + reorder + int8 quantize
// ---------------------------------------------------------------------------
__global__ void wsplit_k(const float* __restrict__ w) {
    int o = blockIdx.x * 256 + threadIdx.x;
    if (o >= COUT_ * CK_) return;
    int cout = o / CK_;
    int r    = o % CK_;                   // = k*256 + c (K-major position)
    int k    = r >> 8;
    int c    = r & 255;
    float v = w[(size_t)cout * CK_ + c * 9 + k];
    __nv_bfloat16 hi = __float2bfloat16(v);
    float hf = __bfloat162float(hi);
    float e  = v - hf;
    g_whi[o] = hi;
    int chunk = r >> 5;
    int pos   = r & 31;
    size_t ib = (size_t)cout * (CK_ * 2) + chunk * 64;
    g_wi8[ib + pos]      = q8(e  * QA_E);   // qeA  (pairs with qBh)
    g_wi8[ib + 32 + pos] = q8(hf * QA_H);   // qAh  (pairs with qeB)
}

// ---------------------------------------------------------------------------
// Kernel 1: deformable im2col -> bf16 hi + int8 (qBh|qeB) columns
// ---------------------------------------------------------------------------
__global__ void im2col_k(const float* __restrict__ x,
                         const float* __restrict__ off)
{
    int idx = blockIdx.x * blockDim.x + threadIdx.x;
    if (idx >= N_ * K_ * P_) return;

    int p  = idx & (P_ - 1);
    int nk = idx >> 12;
    int k  = nk % K_;
    int n  = nk / K_;
    int ho = p >> 6;
    int wo = p & 63;
    int ky = k / 3;
    int kx = k % 3;

    const float* ob = off + ((size_t)n * (2 * K_) + k * 2) * P_;
    float py = (float)(ho - 1 + ky) + ob[p];
    float px = (float)(wo - 1 + kx) + ob[P_ + p];

    float y0f = floorf(py), x0f = floorf(px);
    float ly = py - y0f, lx = px - x0f;
    float hy = 1.0f - ly, hx = 1.0f - lx;
    int y0 = (int)y0f, x0 = (int)x0f;
    int y1 = y0 + 1,   x1 = x0 + 1;

    bool vy0 = ((unsigned)y0 < (unsigned)H_);
    bool vy1 = ((unsigned)y1 < (unsigned)H_);
    bool vx0 = ((unsigned)x0 < (unsigned)W_);
    bool vx1 = ((unsigned)x1 < (unsigned)W_);

    int cy0 = min(max(y0, 0), H_ - 1);
    int cy1 = min(max(y1, 0), H_ - 1);
    int cx0 = min(max(x0, 0), W_ - 1);
    int cx1 = min(max(x1, 0), W_ - 1);

    float w00 = (vy0 && vx0) ? hy * hx : 0.0f;
    float w01 = (vy0 && vx1) ? hy * lx : 0.0f;
    float w10 = (vy1 && vx0) ? ly * hx : 0.0f;
    float w11 = (vy1 && vx1) ? ly * lx : 0.0f;

    int i00 = cy0 * W_ + cx0;
    int i01 = cy0 * W_ + cx1;
    int i10 = cy1 * W_ + cx0;
    int i11 = cy1 * W_ + cx1;

    const float* xb = x + (size_t)n * C_ * (H_ * W_);
    size_t np    = (size_t)(n * P_ + p);
    size_t hbase = np * CK_ + k * 256;              // bf16 hi, K-major
    size_t ibase = np * (CK_ * 2) + (k * 8) * 64;   // int8 pairs, chunk = k*8 + c/32

    union { __nv_bfloat16 h[8]; uint4 v; } bh;
    union { int8_t b[8]; unsigned long long u; } qh, qe;
    for (int c8 = 0; c8 < 32; ++c8) {
        #pragma unroll
        for (int j = 0; j < 8; ++j) {
            const float* xc = xb + (size_t)(c8 * 8 + j) * (H_ * W_);
            float v = w00 * __ldg(xc + i00) + w01 * __ldg(xc + i01)
                    + w10 * __ldg(xc + i10) + w11 * __ldg(xc + i11);
            __nv_bfloat16 h = __float2bfloat16(v);
            float hf = __bfloat162float(h);
            bh.h[j]  = h;
            qh.b[j]  = q8(hf * QB_H);            // qBh
            qe.b[j]  = q8((v - hf) * QB_E);      // qeB
        }
        int cpos  = c8 * 8;                      // channel start (0..248)
        int chunk = cpos >> 5;                   // within this k: 0..7
        int pos   = cpos & 31;                   // 0,8,16,24
        *(uint4*)(g_chi + hbase + cpos) = bh.v;
        size_t ib = ibase + chunk * 64;
        *(unsigned long long*)(g_ci8 + ib + pos)      = qh.u;
        *(unsigned long long*)(g_ci8 + ib + 32 + pos) = qe.u;
    }
}

// ---------------------------------------------------------------------------
// Kernel 2: GEMM = bf16 main (Ah*Bh) + single int8 GEMM for both corrections
// CTA tile 128 cout x 128 pixels, K-chunk 32, 4-stage cp.async pipeline.
// ---------------------------------------------------------------------------
#define PITCH     80            // 64B data + 16B pad, conflict-free
#define A_HI      0
#define A_I8      10240
#define B_HI      20480
#define B_I8      30720
#define STAGE     40960
#define NSTAGE    4
#define SMEM_TOTAL (NSTAGE * STAGE)   // 160 KB

__device__ __forceinline__ void load_stage(uint32_t st, int chunk,
                                           int cout0, int n, int p0, int tid)
{
    // all four planes have 4608-byte rows (CK_ bf16 elems == CK_*2 int8 elems)
    // and a 64-byte chunk offset.
    const size_t cb = (size_t)chunk * 64;
    #pragma unroll
    for (int i = 0; i < 8; ++i) {
        int idx = tid + i * 256;                 // 0..2047
        int region = idx >> 9;                   // 0..3
        int r   = idx & 511;
        int row = r >> 2;                        // 0..127
        int c16 = (r & 3) * 16;                  // 0..48
        const char* src;
        uint32_t dst;
        if (region == 0) {        // A hi (weights bf16)
            src = (const char*)g_whi + (size_t)(cout0 + row) * (CK_ * 2) + cb + c16;
            dst = st + A_HI + row * PITCH + c16;
        } else if (region == 1) { // A int8 [qeA|qAh]
            src = (const char*)g_wi8 + (size_t)(cout0 + row) * (CK_ * 2) + cb + c16;
            dst = st + A_I8 + row * PITCH + c16;
        } else if (region == 2) { // B hi (cols bf16)
            src = (const char*)g_chi + ((size_t)(n * P_ + p0 + row)) * (CK_ * 2) + cb + c16;
            dst = st + B_HI + row * PITCH + c16;
        } else {                  // B int8 [qBh|qeB]
            src = (const char*)g_ci8 + ((size_t)(n * P_ + p0 + row)) * (CK_ * 2) + cb + c16;
            dst = st + B_I8 + row * PITCH + c16;
        }
        cp16(dst, src);
    }
}

__global__ __launch_bounds__(256)
void gemm_k(const float* __restrict__ bias, float* __restrict__ out)
{
    extern __shared__ __align__(128) char smem[];
    const uint32_t sb = smem_to_u32(smem);

    const int tid    = threadIdx.x;
    const int lane   = tid & 31;
    const int wid    = tid >> 5;
    const int warp_m = wid & 1;       // 64-cout half
    const int warp_n = wid >> 1;      // 32-pixel quarter

    const int cout0 = blockIdx.x * 128;
    const int p0    = blockIdx.y * 128;
    const int n     = blockIdx.z;

    float   d [4][4][4];
    int32_t di[4][4][4];
    #pragma unroll
    for (int mi = 0; mi < 4; ++mi)
        #pragma unroll
        for (int ni = 0; ni < 4; ++ni)
            #pragma unroll
            for (int j = 0; j < 4; ++j) { d[mi][ni][j] = 0.0f; di[mi][ni][j] = 0; }

    #pragma unroll
    for (int s = 0; s < NSTAGE - 1; ++s) {
        load_stage(sb + s * STAGE, s, cout0, n, p0, tid);
        cp_commit();
    }

    // ldmatrix lane addressing (identical pattern for bf16-k16 and i8-k32)
    const int a_row = (lane & 15);
    const int a_c16 = (lane >> 4) << 4;
    const int b_row = (lane & 7) + ((lane >> 4) << 3);
    const int b_c16 = ((lane >> 3) & 1) << 4;

    for (int c = 0; c < NCHUNK; ++c) {
        cp_wait<NSTAGE - 2>();
        __syncthreads();

        // prefetch next stage first (writes stage consumed at iter c-1: safe)
        if (c + NSTAGE - 1 < NCHUNK)
            load_stage(sb + ((c + NSTAGE - 1) & (NSTAGE - 1)) * STAGE,
                       c + NSTAGE - 1, cout0, n, p0, tid);
        cp_commit();

        const uint32_t st = sb + (c & (NSTAGE - 1)) * STAGE;

        // ---- bf16 main: Ah*Bh, two k16 steps ----
        #pragma unroll
        for (int s = 0; s < 2; ++s) {
            uint32_t ah[4][4];
            #pragma unroll
            for (int mi = 0; mi < 4; ++mi)
                ldsm4(ah[mi], st + A_HI
                      + (warp_m * 64 + mi * 16 + a_row) * PITCH + s * 32 + a_c16);
            uint32_t bhf[2][4];
            #pragma unroll
            for (int np = 0; np < 2; ++np)
                ldsm4(bhf[np], st + B_HI
                      + (warp_n * 32 + np * 16 + b_row) * PITCH + s * 32 + b_c16);
            #pragma unroll
            for (int mi = 0; mi < 4; ++mi)
                #pragma unroll
                for (int ni = 0; ni < 4; ++ni) {
                    const int np = ni >> 1, sub = (ni & 1) * 2;
                    mma16816(d[mi][ni], ah[mi], bhf[np][sub], bhf[np][sub + 1]);
                }
        }

        // ---- int8 corrections: [qeA|qAh] x [qBh|qeB], two k32 segments ----
        #pragma unroll
        for (int g = 0; g < 2; ++g) {
            uint32_t ai[4][4];
            #pragma unroll
            for (int mi = 0; mi < 4; ++mi)
                ldsm4(ai[mi], st + A_I8
                      + (warp_m * 64 + mi * 16 + a_row) * PITCH + g * 32 + a_c16);
            uint32_t bif[2][4];
            #pragma unroll
            for (int np = 0; np < 2; ++np)
                ldsm4(bif[np], st + B_I8
                      + (warp_n * 32 + np * 16 + b_row) * PITCH + g * 32 + b_c16);
            #pragma unroll
            for (int mi = 0; mi < 4; ++mi)
                #pragma unroll
                for (int ni = 0; ni < 4; ++ni) {
                    const int np = ni >> 1, sub = (ni & 1) * 2;
                    mma16832i(di[mi][ni], ai[mi], bif[np][sub], bif[np][sub + 1]);
                }
        }
    }

    // epilogue: main + INV_Q*int_corr + bias
    const int gr = lane >> 2;
    const int gc = (lane & 3) * 2;
    #pragma unroll
    for (int mi = 0; mi < 4; ++mi) {
        const int cout = cout0 + warp_m * 64 + mi * 16 + gr;
        const float bv0 = __ldg(bias + cout);
        const float bv1 = __ldg(bias + cout + 8);
        float* base = out + ((size_t)n * COUT_ + cout) * P_;
        #pragma unroll
        for (int ni = 0; ni < 4; ++ni) {
            const int px = p0 + warp_n * 32 + ni * 8 + gc;
            float2 v0, v1;
            v0.x = d[mi][ni][0] + INV_Q * (float)di[mi][ni][0] + bv0;
            v0.y = d[mi][ni][1] + INV_Q * (float)di[mi][ni][1] + bv0;
            v1.x = d[mi][ni][2] + INV_Q * (float)di[mi][ni][2] + bv1;
            v1.y = d[mi][ni][3] + INV_Q * (float)di[mi][ni][3] + bv1;
            *(float2*)(base + px)          = v0;
            *(float2*)(base + 8 * P_ + px) = v1;
        }
    }
}

// ---------------------------------------------------------------------------
extern "C" void kernel_launch(void* const* d_in, const int* in_sizes, int n_in,
                              void* d_out, int out_size)
{
    const float* x    = (const float*)d_in[0];
    const float* off  = (const float*)d_in[1];
    const float* wgt  = (const float*)d_in[2];
    const float* bias = (const float*)d_in[3];
    float* out = (float*)d_out;

    static bool attr_set = false;
    if (!attr_set) {
        cudaFuncSetAttribute(gemm_k, cudaFuncAttributeMaxDynamicSharedMemorySize,
                             SMEM_TOTAL);
        attr_set = true;
    }

    wsplit_k<<<(COUT_ * CK_ + 255) / 256, 256>>>(wgt);
    im2col_k<<<(N_ * K_ * P_) / 256, 256>>>(x, off);

    dim3 grid(COUT_ / 128, P_ / 128, N_);   // (2, 32, 8)
    gemm_k<<<grid, 256, SMEM_TOTAL>>>(bias, out);
}

// round 7
// speedup vs baseline: 3.5565x; 3.5565x over previous
#include <cuda_runtime.h>
#include <cuda_fp16.h>
#include <cstdint>
#include <math.h>

#define N_    8
#define C_    256
#define H_    64
#define W_    64
#define K_    9
#define P_    4096          // 64*64
#define CK_   2304          // C_*K_
#define COUT_ 256
#define NCHUNK 72           // CK_/32

// ------------------------------- scratch ------------------------------------
// cols fp16, K-major layout [n][p][k*256+c]
__device__ __half g_ch[(size_t)N_ * P_ * CK_];
// weights fp16, reordered to [cout][k*256+c]
__device__ __half g_wh[COUT_ * CK_];

// ---------------- small PTX helpers (family-agnostic only) ------------------
__device__ __forceinline__ uint32_t smem_to_u32(const void* p) {
    uint32_t a;
    asm("{ .reg .u64 t; cvta.to.shared.u64 t, %1; cvt.u32.u64 %0, t; }"
        : "=r"(a) : "l"(p));
    return a;
}
__device__ __forceinline__ void cp16(uint32_t dst, const void* src) {
    asm volatile("cp.async.cg.shared.global [%0], [%1], 16;"
                 :: "r"(dst), "l"(src));
}
__device__ __forceinline__ void cp_commit() {
    asm volatile("cp.async.commit_group;" ::: "memory");
}
template <int NN>
__device__ __forceinline__ void cp_wait() {
    asm volatile("cp.async.wait_group %0;" :: "n"(NN) : "memory");
}
__device__ __forceinline__ void ldsm4(uint32_t* r, uint32_t addr) {
    asm volatile("ldmatrix.sync.aligned.m8n8.x4.shared.b16 {%0,%1,%2,%3}, [%4];"
        : "=r"(r[0]), "=r"(r[1]), "=r"(r[2]), "=r"(r[3]) : "r"(addr));
}
__device__ __forceinline__ void mma16816h(float* d, const uint32_t* a,
                                          uint32_t b0, uint32_t b1) {
    asm volatile("mma.sync.aligned.m16n8k16.row.col.f32.f16.f16.f32 "
        "{%0,%1,%2,%3}, {%4,%5,%6,%7}, {%8,%9}, {%0,%1,%2,%3};"
        : "+f"(d[0]), "+f"(d[1]), "+f"(d[2]), "+f"(d[3])
        : "r"(a[0]), "r"(a[1]), "r"(a[2]), "r"(a[3]), "r"(b0), "r"(b1));
}

// ---------------------------------------------------------------------------
// Kernel 0: weight convert + reorder: g_wh[cout][k*256+c] = w[cout][c][k]
// ---------------------------------------------------------------------------
__global__ void wsplit_k(const float* __restrict__ w) {
    int o = blockIdx.x * 256 + threadIdx.x;
    if (o >= COUT_ * CK_) return;
    int cout = o / CK_;
    int r    = o % CK_;
    int k    = r >> 8;
    int c    = r & 255;
    g_wh[o] = __float2half_rn(w[(size_t)cout * CK_ + c * 9 + k]);
}

// ---------------------------------------------------------------------------
// Kernel 1: deformable im2col -> fp16 columns, K-major per pixel
// ---------------------------------------------------------------------------
__global__ void im2col_k(const float* __restrict__ x,
                         const float* __restrict__ off)
{
    int idx = blockIdx.x * blockDim.x + threadIdx.x;
    if (idx >= N_ * K_ * P_) return;

    int p  = idx & (P_ - 1);
    int nk = idx >> 12;
    int k  = nk % K_;
    int n  = nk / K_;
    int ho = p >> 6;
    int wo = p & 63;
    int ky = k / 3;
    int kx = k % 3;

    const float* ob = off + ((size_t)n * (2 * K_) + k * 2) * P_;
    float py = (float)(ho - 1 + ky) + ob[p];
    float px = (float)(wo - 1 + kx) + ob[P_ + p];

    float y0f = floorf(py), x0f = floorf(px);
    float ly = py - y0f, lx = px - x0f;
    float hy = 1.0f - ly, hx = 1.0f - lx;
    int y0 = (int)y0f, x0 = (int)x0f;
    int y1 = y0 + 1,   x1 = x0 + 1;

    bool vy0 = ((unsigned)y0 < (unsigned)H_);
    bool vy1 = ((unsigned)y1 < (unsigned)H_);
    bool vx0 = ((unsigned)x0 < (unsigned)W_);
    bool vx1 = ((unsigned)x1 < (unsigned)W_);

    int cy0 = min(max(y0, 0), H_ - 1);
    int cy1 = min(max(y1, 0), H_ - 1);
    int cx0 = min(max(x0, 0), W_ - 1);
    int cx1 = min(max(x1, 0), W_ - 1);

    float w00 = (vy0 && vx0) ? hy * hx : 0.0f;
    float w01 = (vy0 && vx1) ? hy * lx : 0.0f;
    float w10 = (vy1 && vx0) ? ly * hx : 0.0f;
    float w11 = (vy1 && vx1) ? ly * lx : 0.0f;

    int i00 = cy0 * W_ + cx0;
    int i01 = cy0 * W_ + cx1;
    int i10 = cy1 * W_ + cx0;
    int i11 = cy1 * W_ + cx1;

    const float* xb = x + (size_t)n * C_ * (H_ * W_);
    size_t obase = ((size_t)(n * P_ + p)) * CK_ + k * 256;

    union { __half h[8]; uint4 v; } bh;
    for (int c8 = 0; c8 < 32; ++c8) {
        #pragma unroll
        for (int j = 0; j < 8; ++j) {
            const float* xc = xb + (size_t)(c8 * 8 + j) * (H_ * W_);
            float v = w00 * __ldg(xc + i00) + w01 * __ldg(xc + i01)
                    + w10 * __ldg(xc + i10) + w11 * __ldg(xc + i11);
            bh.h[j] = __float2half_rn(v);
        }
        *(uint4*)(g_ch + obase + c8 * 8) = bh.v;
    }
}

// ---------------------------------------------------------------------------
// Kernel 2: single-pass fp16 mma.sync GEMM
// out[n][cout][p], D[cout, pixel] = W[cout, 2304] @ cols[pixel, 2304]^T
// CTA tile 128 cout x 128 pixels, K-chunk 32, 4-stage cp.async pipeline.
// 80 KB smem -> 2 CTAs/SM.
// ---------------------------------------------------------------------------
#define PITCH     80            // 64B data + 16B pad, conflict-free ldmatrix
#define A_OFF     0
#define B_OFF     10240
#define STAGE     20480
#define NSTAGE    4
#define SMEM_TOTAL (NSTAGE * STAGE)   // 80 KB

__device__ __forceinline__ void load_stage(uint32_t st, int chunk,
                                           int cout0, int n, int p0, int tid)
{
    const size_t cb = (size_t)chunk * 64;        // byte offset in 4608 B row
    #pragma unroll
    for (int i = 0; i < 4; ++i) {
        int idx = tid + i * 256;                 // 0..1023
        int region = idx >> 9;                   // 0=A(weights), 1=B(cols)
        int r   = idx & 511;
        int row = r >> 2;                        // 0..127
        int c16 = (r & 3) * 16;                  // 0..48
        if (region == 0) {
            const char* src = (const char*)g_wh
                + (size_t)(cout0 + row) * (CK_ * 2) + cb + c16;
            cp16(st + A_OFF + row * PITCH + c16, src);
        } else {
            const char* src = (const char*)g_ch
                + ((size_t)(n * P_ + p0 + row)) * (CK_ * 2) + cb + c16;
            cp16(st + B_OFF + row * PITCH + c16, src);
        }
    }
}

__global__ __launch_bounds__(256)
void gemm_k(const float* __restrict__ bias, float* __restrict__ out)
{
    extern __shared__ __align__(128) char smem[];
    const uint32_t sb = smem_to_u32(smem);

    const int tid    = threadIdx.x;
    const int lane   = tid & 31;
    const int wid    = tid >> 5;
    const int warp_m = wid & 1;       // 64-cout half
    const int warp_n = wid >> 1;      // 32-pixel quarter

    const int cout0 = blockIdx.x * 128;
    const int p0    = blockIdx.y * 128;
    const int n     = blockIdx.z;

    float d[4][4][4];
    #pragma unroll
    for (int mi = 0; mi < 4; ++mi)
        #pragma unroll
        for (int ni = 0; ni < 4; ++ni)
            #pragma unroll
            for (int j = 0; j < 4; ++j) d[mi][ni][j] = 0.0f;

    #pragma unroll
    for (int s = 0; s < NSTAGE - 1; ++s) {
        load_stage(sb + s * STAGE, s, cout0, n, p0, tid);
        cp_commit();
    }

    const int a_row = (lane & 15);
    const int a_c16 = (lane >> 4) << 4;
    const int b_row = (lane & 7) + ((lane >> 4) << 3);
    const int b_c16 = ((lane >> 3) & 1) << 4;

    for (int c = 0; c < NCHUNK; ++c) {
        cp_wait<NSTAGE - 2>();
        __syncthreads();

        const uint32_t st = sb + (c & (NSTAGE - 1)) * STAGE;

        #pragma unroll
        for (int s = 0; s < 2; ++s) {           // two k16 steps per chunk
            uint32_t ah[4][4];
            #pragma unroll
            for (int mi = 0; mi < 4; ++mi)
                ldsm4(ah[mi], st + A_OFF
                      + (warp_m * 64 + mi * 16 + a_row) * PITCH + s * 32 + a_c16);
            uint32_t bhf[2][4];
            #pragma unroll
            for (int np = 0; np < 2; ++np)
                ldsm4(bhf[np], st + B_OFF
                      + (warp_n * 32 + np * 16 + b_row) * PITCH + s * 32 + b_c16);
            #pragma unroll
            for (int mi = 0; mi < 4; ++mi)
                #pragma unroll
                for (int ni = 0; ni < 4; ++ni) {
                    const int np = ni >> 1, sub = (ni & 1) * 2;
                    mma16816h(d[mi][ni], ah[mi], bhf[np][sub], bhf[np][sub + 1]);
                }
        }

        __syncthreads();
        if (c + NSTAGE - 1 < NCHUNK)
            load_stage(sb + ((c + NSTAGE - 1) & (NSTAGE - 1)) * STAGE,
                       c + NSTAGE - 1, cout0, n, p0, tid);
        cp_commit();     // unconditional: uniform wait_group bookkeeping
    }

    // epilogue: D fragment (row=cout, col=pixel) -> out[n][cout][p] + bias
    const int gr = lane >> 2;
    const int gc = (lane & 3) * 2;
    #pragma unroll
    for (int mi = 0; mi < 4; ++mi) {
        const int cout = cout0 + warp_m * 64 + mi * 16 + gr;
        const float bv0 = __ldg(bias + cout);
        const float bv1 = __ldg(bias + cout + 8);
        float* base = out + ((size_t)n * COUT_ + cout) * P_;
        #pragma unroll
        for (int ni = 0; ni < 4; ++ni) {
            const int px = p0 + warp_n * 32 + ni * 8 + gc;
            float2 v0 = make_float2(d[mi][ni][0] + bv0, d[mi][ni][1] + bv0);
            float2 v1 = make_float2(d[mi][ni][2] + bv1, d[mi][ni][3] + bv1);
            *(float2*)(base + px)          = v0;
            *(float2*)(base + 8 * P_ + px) = v1;
        }
    }
}

// ---------------------------------------------------------------------------
extern "C" void kernel_launch(void* const* d_in, const int* in_sizes, int n_in,
                              void* d_out, int out_size)
{
    const float* x    = (const float*)d_in[0];
    const float* off  = (const float*)d_in[1];
    const float* wgt  = (const float*)d_in[2];
    const float* bias = (const float*)d_in[3];
    float* out = (float*)d_out;

    static bool attr_set = false;
    if (!attr_set) {
        cudaFuncSetAttribute(gemm_k, cudaFuncAttributeMaxDynamicSharedMemorySize,
                             SMEM_TOTAL);
        attr_set = true;
    }

    wsplit_k<<<(COUT_ * CK_ + 255) / 256, 256>>>(wgt);
    im2col_k<<<(N_ * K_ * P_) / 256, 256>>>(x, off);

    dim3 grid(COUT_ / 128, P_ / 128, N_);   // (2, 32, 8)
    gemm_k<<<grid, 256, SMEM_TOTAL>>>(bias, out);
}

// round 8
// speedup vs baseline: 5.5655x; 1.5649x over previous
#include <cuda_runtime.h>
#include <cuda_fp16.h>
#include <cstdint>
#include <math.h>

#define N_    8
#define C_    256
#define H_    64
#define W_    64
#define K_    9
#define P_    4096          // 64*64
#define CK_   2304          // C_*K_
#define COUT_ 256
#define NCHUNK 72           // CK_/32

// ------------------------------- scratch ------------------------------------
// x transposed to NHWC fp16: g_xh[n][s][c], s = y*64+x
__device__ __half g_xh[(size_t)N_ * P_ * C_];
// cols fp16, K-major layout [n][p][k*256+c]
__device__ __half g_ch[(size_t)N_ * P_ * CK_];
// weights fp16, reordered to [cout][k*256+c]
__device__ __half g_wh[COUT_ * CK_];

// ---------------- small PTX helpers (family-agnostic only) ------------------
__device__ __forceinline__ uint32_t smem_to_u32(const void* p) {
    uint32_t a;
    asm("{ .reg .u64 t; cvta.to.shared.u64 t, %1; cvt.u32.u64 %0, t; }"
        : "=r"(a) : "l"(p));
    return a;
}
__device__ __forceinline__ void cp16(uint32_t dst, const void* src) {
    asm volatile("cp.async.cg.shared.global [%0], [%1], 16;"
                 :: "r"(dst), "l"(src));
}
__device__ __forceinline__ void cp_commit() {
    asm volatile("cp.async.commit_group;" ::: "memory");
}
template <int NN>
__device__ __forceinline__ void cp_wait() {
    asm volatile("cp.async.wait_group %0;" :: "n"(NN) : "memory");
}
__device__ __forceinline__ void ldsm4(uint32_t* r, uint32_t addr) {
    asm volatile("ldmatrix.sync.aligned.m8n8.x4.shared.b16 {%0,%1,%2,%3}, [%4];"
        : "=r"(r[0]), "=r"(r[1]), "=r"(r[2]), "=r"(r[3]) : "r"(addr));
}
__device__ __forceinline__ void mma16816h(float* d, const uint32_t* a,
                                          uint32_t b0, uint32_t b1) {
    asm volatile("mma.sync.aligned.m16n8k16.row.col.f32.f16.f16.f32 "
        "{%0,%1,%2,%3}, {%4,%5,%6,%7}, {%8,%9}, {%0,%1,%2,%3};"
        : "+f"(d[0]), "+f"(d[1]), "+f"(d[2]), "+f"(d[3])
        : "r"(a[0]), "r"(a[1]), "r"(a[2]), "r"(a[3]), "r"(b0), "r"(b1));
}

// ---------------------------------------------------------------------------
// Kernel -1: x NCHW fp32 -> NHWC fp16 (smem transpose, tile 64ch x 32sp)
// ---------------------------------------------------------------------------
__global__ __launch_bounds__(256)
void nhwc_k(const float* __restrict__ x) {
    __shared__ float sm[64][33];
    const int n  = blockIdx.z;
    const int c0 = blockIdx.y * 64;
    const int s0 = blockIdx.x * 32;
    const int tx = threadIdx.x & 31;
    const int ty = threadIdx.x >> 5;     // 0..7

    #pragma unroll
    for (int i = 0; i < 8; ++i) {
        int c = i * 8 + ty;
        sm[c][tx] = x[((size_t)n * C_ + c0 + c) * P_ + s0 + tx];
    }
    __syncthreads();
    #pragma unroll
    for (int i = 0; i < 4; ++i) {
        int s = i * 8 + ty;
        __half2 h = __floats2half2_rn(sm[2 * tx][s], sm[2 * tx + 1][s]);
        *(__half2*)(g_xh + ((size_t)(n * P_ + s0 + s)) * C_ + c0 + 2 * tx) = h;
    }
}

// ---------------------------------------------------------------------------
// Kernel 0: weight convert + reorder: g_wh[cout][k*256+c] = w[cout][c][k]
// ---------------------------------------------------------------------------
__global__ void wsplit_k(const float* __restrict__ w) {
    int o = blockIdx.x * 256 + threadIdx.x;
    if (o >= COUT_ * CK_) return;
    int cout = o / CK_;
    int r    = o % CK_;
    int k    = r >> 8;
    int c    = r & 255;
    g_wh[o] = __float2half_rn(w[(size_t)cout * CK_ + c * 9 + k]);
}

// ---------------------------------------------------------------------------
// Kernel 1: deformable im2col, warp-per-(n,k,p), lane = 8-channel block.
// 4 coalesced LDG.128 corner reads per lane from NHWC fp16 x.
// ---------------------------------------------------------------------------
__global__ __launch_bounds__(256)
void im2col_k(const float* __restrict__ off)
{
    const int lane = threadIdx.x & 31;
    const int wib  = threadIdx.x >> 5;        // 0..7
    const int bid  = blockIdx.x;              // 0..36863
    const int p    = (bid & 511) * 8 + wib;   // 8 consecutive pixels per block
    const int k    = (bid >> 9) % 9;
    const int n    = bid / (512 * 9);

    const int ho = p >> 6;
    const int wo = p & 63;
    const int ky = k / 3;
    const int kx = k % 3;

    const float* ob = off + ((size_t)n * (2 * K_) + k * 2) * P_;
    float py = (float)(ho - 1 + ky) + __ldg(ob + p);        // broadcast loads
    float px = (float)(wo - 1 + kx) + __ldg(ob + P_ + p);

    float y0f = floorf(py), x0f = floorf(px);
    float ly = py - y0f, lx = px - x0f;
    float hy = 1.0f - ly, hx = 1.0f - lx;
    int y0 = (int)y0f, x0 = (int)x0f;
    int y1 = y0 + 1,   x1 = x0 + 1;

    bool vy0 = ((unsigned)y0 < (unsigned)H_);
    bool vy1 = ((unsigned)y1 < (unsigned)H_);
    bool vx0 = ((unsigned)x0 < (unsigned)W_);
    bool vx1 = ((unsigned)x1 < (unsigned)W_);

    int cy0 = min(max(y0, 0), H_ - 1);
    int cy1 = min(max(y1, 0), H_ - 1);
    int cx0 = min(max(x0, 0), W_ - 1);
    int cx1 = min(max(x1, 0), W_ - 1);

    const float w00 = (vy0 && vx0) ? hy * hx : 0.0f;
    const float w01 = (vy0 && vx1) ? hy * lx : 0.0f;
    const float w10 = (vy1 && vx0) ? ly * hx : 0.0f;
    const float w11 = (vy1 && vx1) ? ly * lx : 0.0f;

    const __half* xb = g_xh + (size_t)n * P_ * C_;
    const uint4* r00 = (const uint4*)(xb + (size_t)(cy0 * W_ + cx0) * C_) + lane;
    const uint4* r01 = (const uint4*)(xb + (size_t)(cy0 * W_ + cx1) * C_) + lane;
    const uint4* r10 = (const uint4*)(xb + (size_t)(cy1 * W_ + cx0) * C_) + lane;
    const uint4* r11 = (const uint4*)(xb + (size_t)(cy1 * W_ + cx1) * C_) + lane;

    uint4 a00 = __ldg(r00);
    uint4 a01 = __ldg(r01);
    uint4 a10 = __ldg(r10);
    uint4 a11 = __ldg(r11);

    union { __half2 h[4]; uint4 v; } o;
    const __half2* h00 = (const __half2*)&a00;
    const __half2* h01 = (const __half2*)&a01;
    const __half2* h10 = (const __half2*)&a10;
    const __half2* h11 = (const __half2*)&a11;

    #pragma unroll
    for (int j = 0; j < 4; ++j) {
        float2 f00 = __half22float2(h00[j]);
        float2 f01 = __half22float2(h01[j]);
        float2 f10 = __half22float2(h10[j]);
        float2 f11 = __half22float2(h11[j]);
        float2 r;
        r.x = w00 * f00.x + w01 * f01.x + w10 * f10.x + w11 * f11.x;
        r.y = w00 * f00.y + w01 * f01.y + w10 * f10.y + w11 * f11.y;
        o.h[j] = __float22half2_rn(r);
    }

    size_t obase = ((size_t)(n * P_ + p)) * CK_ + k * 256;
    *(uint4*)(g_ch + obase + lane * 8) = o.v;
}

// ---------------------------------------------------------------------------
// Kernel 2: single-pass fp16 mma.sync GEMM
// CTA tile 128 cout x 128 pixels, K-chunk 32, 4-stage cp.async pipeline,
// one barrier per chunk. 80 KB smem -> 2 CTAs/SM.
// ---------------------------------------------------------------------------
#define PITCH     80            // 64B data + 16B pad, conflict-free ldmatrix
#define A_OFF     0
#define B_OFF     10240
#define STAGE     20480
#define NSTAGE    4
#define SMEM_TOTAL (NSTAGE * STAGE)   // 80 KB

__device__ __forceinline__ void load_stage(uint32_t st, int chunk,
                                           int cout0, int n, int p0, int tid)
{
    const size_t cb = (size_t)chunk * 64;        // byte offset in 4608 B row
    #pragma unroll
    for (int i = 0; i < 4; ++i) {
        int idx = tid + i * 256;                 // 0..1023
        int region = idx >> 9;                   // 0=A(weights), 1=B(cols)
        int r   = idx & 511;
        int row = r >> 2;                        // 0..127
        int c16 = (r & 3) * 16;                  // 0..48
        if (region == 0) {
            const char* src = (const char*)g_wh
                + (size_t)(cout0 + row) * (CK_ * 2) + cb + c16;
            cp16(st + A_OFF + row * PITCH + c16, src);
        } else {
            const char* src = (const char*)g_ch
                + ((size_t)(n * P_ + p0 + row)) * (CK_ * 2) + cb + c16;
            cp16(st + B_OFF + row * PITCH + c16, src);
        }
    }
}

__global__ __launch_bounds__(256)
void gemm_k(const float* __restrict__ bias, float* __restrict__ out)
{
    extern __shared__ __align__(128) char smem[];
    const uint32_t sb = smem_to_u32(smem);

    const int tid    = threadIdx.x;
    const int lane   = tid & 31;
    const int wid    = tid >> 5;
    const int warp_m = wid & 1;       // 64-cout half
    const int warp_n = wid >> 1;      // 32-pixel quarter

    const int cout0 = blockIdx.x * 128;
    const int p0    = blockIdx.y * 128;
    const int n     = blockIdx.z;

    float d[4][4][4];
    #pragma unroll
    for (int mi = 0; mi < 4; ++mi)
        #pragma unroll
        for (int ni = 0; ni < 4; ++ni)
            #pragma unroll
            for (int j = 0; j < 4; ++j) d[mi][ni][j] = 0.0f;

    #pragma unroll
    for (int s = 0; s < NSTAGE - 1; ++s) {
        load_stage(sb + s * STAGE, s, cout0, n, p0, tid);
        cp_commit();
    }

    const int a_row = (lane & 15);
    const int a_c16 = (lane >> 4) << 4;
    const int b_row = (lane & 7) + ((lane >> 4) << 3);
    const int b_c16 = ((lane >> 3) & 1) << 4;

    for (int c = 0; c < NCHUNK; ++c) {
        cp_wait<NSTAGE - 2>();
        __syncthreads();

        // prefetch stage (c+3)&3: last read in iter c-1, protected by the
        // barrier above -> single barrier per chunk is sufficient.
        if (c + NSTAGE - 1 < NCHUNK)
            load_stage(sb + ((c + NSTAGE - 1) & (NSTAGE - 1)) * STAGE,
                       c + NSTAGE - 1, cout0, n, p0, tid);
        cp_commit();

        const uint32_t st = sb + (c & (NSTAGE - 1)) * STAGE;

        #pragma unroll
        for (int s = 0; s < 2; ++s) {           // two k16 steps per chunk
            uint32_t ah[4][4];
            #pragma unroll
            for (int mi = 0; mi < 4; ++mi)
                ldsm4(ah[mi], st + A_OFF
                      + (warp_m * 64 + mi * 16 + a_row) * PITCH + s * 32 + a_c16);
            uint32_t bhf[2][4];
            #pragma unroll
            for (int np = 0; np < 2; ++np)
                ldsm4(bhf[np], st + B_OFF
                      + (warp_n * 32 + np * 16 + b_row) * PITCH + s * 32 + b_c16);
            #pragma unroll
            for (int mi = 0; mi < 4; ++mi)
                #pragma unroll
                for (int ni = 0; ni < 4; ++ni) {
                    const int np = ni >> 1, sub = (ni & 1) * 2;
                    mma16816h(d[mi][ni], ah[mi], bhf[np][sub], bhf[np][sub + 1]);
                }
        }
    }

    // epilogue: D fragment (row=cout, col=pixel) -> out[n][cout][p] + bias
    const int gr = lane >> 2;
    const int gc = (lane & 3) * 2;
    #pragma unroll
    for (int mi = 0; mi < 4; ++mi) {
        const int cout = cout0 + warp_m * 64 + mi * 16 + gr;
        const float bv0 = __ldg(bias + cout);
        const float bv1 = __ldg(bias + cout + 8);
        float* base = out + ((size_t)n * COUT_ + cout) * P_;
        #pragma unroll
        for (int ni = 0; ni < 4; ++ni) {
            const int px = p0 + warp_n * 32 + ni * 8 + gc;
            float2 v0 = make_float2(d[mi][ni][0] + bv0, d[mi][ni][1] + bv0);
            float2 v1 = make_float2(d[mi][ni][2] + bv1, d[mi][ni][3] + bv1);
            *(float2*)(base + px)          = v0;
            *(float2*)(base + 8 * P_ + px) = v1;
        }
    }
}

// ---------------------------------------------------------------------------
extern "C" void kernel_launch(void* const* d_in, const int* in_sizes, int n_in,
                              void* d_out, int out_size)
{
    const float* x    = (const float*)d_in[0];
    const float* off  = (const float*)d_in[1];
    const float* wgt  = (const float*)d_in[2];
    const float* bias = (const float*)d_in[3];
    float* out = (float*)d_out;

    static bool attr_set = false;
    if (!attr_set) {
        cudaFuncSetAttribute(gemm_k, cudaFuncAttributeMaxDynamicSharedMemorySize,
                             SMEM_TOTAL);
        attr_set = true;
    }

    dim3 tgrid(P_ / 32, C_ / 64, N_);       // (128, 4, 8)
    nhwc_k<<<tgrid, 256>>>(x);
    wsplit_k<<<(COUT_ * CK_ + 255) / 256, 256>>>(wgt);
    im2col_k<<<N_ * K_ * P_ / 8, 256>>>(off);

    dim3 grid(COUT_ / 128, P_ / 128, N_);   // (2, 32, 8)
    gemm_k<<<grid, 256, SMEM_TOTAL>>>(bias, out);
}